// round 1
// baseline (speedup 1.0000x reference)
#include <cuda_runtime.h>
#include <cuda_bf16.h>
#include <math.h>

// Problem dims (fixed by setup_inputs)
#define NB   16
#define CC   4
#define HH   256
#define WW   256
#define HW   (HH*WW)          // 65536
#define CHW  (CC*HW)          // 262144
#define TOT  (NB*CHW)         // 4194304
#define NHW  (NB*HW)          // 1048576

#define FINF 1e10f

// Scratch (static device arrays — no allocation)
__device__ float g_fA[TOT];
__device__ float g_fB[TOT];
__device__ double g_num;
__device__ double g_den;

// ---------------------------------------------------------------------------
// k0: zero the accumulators (must run every launch for determinism)
// ---------------------------------------------------------------------------
__global__ void k_init() {
    g_num = 0.0;
    g_den = 0.0;
}

// ---------------------------------------------------------------------------
// k1: build f0 from target and do the C-axis min-plus pass (length 4, exact)
// one thread per (n,h,w) pixel
// ---------------------------------------------------------------------------
__global__ void k_cpass(const int* __restrict__ target, float* __restrict__ fA) {
    int p = blockIdx.x * blockDim.x + threadIdx.x;
    if (p >= NHW) return;
    int n   = p >> 16;              // p / HW
    int rem = p & (HW - 1);
    int base = (n << 18) + rem;     // n*CHW + h*W + w

    float f0[CC];
#pragma unroll
    for (int c = 0; c < CC; ++c) {
        int t = target[base + c * HW];
        f0[c] = (t == 0) ? FINF : 0.0f;
    }
#pragma unroll
    for (int c = 0; c < CC; ++c) {
        float m = FINF;
#pragma unroll
        for (int j = 0; j < CC; ++j) {
            int d = c - j;
            m = fminf(m, f0[j] + (float)(d * d));
        }
        fA[base + c * HW] = m;
    }
}

// ---------------------------------------------------------------------------
// k2: H-axis min-plus pass, exact expanding-window search.
//     out[i] = min_j (i-j)^2 + f[j]; stop when r^2 >= current min (exact,
//     since f >= 0 so farther candidates cannot improve).
// ---------------------------------------------------------------------------
__global__ void k_hpass(const float* __restrict__ fin, float* __restrict__ fout) {
    int idx = blockIdx.x * blockDim.x + threadIdx.x;
    if (idx >= TOT) return;
    int h = (idx >> 8) & 255;

    float m = fin[idx];
    int rlo = h;             // max steps toward smaller h
    int rhi = (HH - 1) - h;  // max steps toward larger h
    int rmax = rlo > rhi ? rlo : rhi;

    for (int r = 1; r <= rmax; ++r) {
        float r2 = (float)(r * r);
        if (r2 >= m) break;
        if (r <= rlo) m = fminf(m, __ldg(&fin[idx - (r << 8)]) + r2);
        if (r <= rhi) m = fminf(m, __ldg(&fin[idx + (r << 8)]) + r2);
    }
    fout[idx] = m;
}

// ---------------------------------------------------------------------------
// k3: W-axis min-plus pass (stride 1), same exact expanding search
// ---------------------------------------------------------------------------
__global__ void k_wpass(const float* __restrict__ fin, float* __restrict__ fout) {
    int idx = blockIdx.x * blockDim.x + threadIdx.x;
    if (idx >= TOT) return;
    int w = idx & 255;

    float m = fin[idx];
    int rlo = w;
    int rhi = (WW - 1) - w;
    int rmax = rlo > rhi ? rlo : rhi;

    for (int r = 1; r <= rmax; ++r) {
        float r2 = (float)(r * r);
        if (r2 >= m) break;
        if (r <= rlo) m = fminf(m, __ldg(&fin[idx - r]) + r2);
        if (r <= rhi) m = fminf(m, __ldg(&fin[idx + r]) + r2);
    }
    fout[idx] = m;
}

// ---------------------------------------------------------------------------
// k4: softmax over C (4 classes) * dist, reduce numerator & denominator
// ---------------------------------------------------------------------------
__global__ void k_reduce(const float* __restrict__ pred,
                         const float* __restrict__ fsq) {
    float num = 0.0f, den = 0.0f;

    for (int p = blockIdx.x * blockDim.x + threadIdx.x; p < NHW;
         p += gridDim.x * blockDim.x) {
        int n   = p >> 16;
        int rem = p & (HW - 1);
        int base = (n << 18) + rem;

        float pr[CC], d[CC];
#pragma unroll
        for (int c = 0; c < CC; ++c) {
            pr[c] = pred[base + c * HW];
            d[c]  = sqrtf(fsq[base + c * HW]);
        }
        float mx = fmaxf(fmaxf(pr[0], pr[1]), fmaxf(pr[2], pr[3]));
        float e0 = expf(pr[0] - mx);
        float e1 = expf(pr[1] - mx);
        float e2 = expf(pr[2] - mx);
        float e3 = expf(pr[3] - mx);
        float s  = e0 + e1 + e2 + e3;
        num += (e0 * d[0] + e1 * d[1] + e2 * d[2] + e3 * d[3]) / s;
        den += d[0] + d[1] + d[2] + d[3];
    }

    // block reduction
    __shared__ float snum[256];
    __shared__ float sden[256];
    int t = threadIdx.x;
    snum[t] = num;
    sden[t] = den;
    __syncthreads();
    for (int off = 128; off > 0; off >>= 1) {
        if (t < off) {
            snum[t] += snum[t + off];
            sden[t] += sden[t + off];
        }
        __syncthreads();
    }
    if (t == 0) {
        atomicAdd(&g_num, (double)snum[0]);
        atomicAdd(&g_den, (double)sden[0]);
    }
}

// ---------------------------------------------------------------------------
// k5: final scalar
// ---------------------------------------------------------------------------
__global__ void k_final(float* __restrict__ out) {
    out[0] = (float)(g_num / (g_den + 1e-10));
}

// ---------------------------------------------------------------------------
extern "C" void kernel_launch(void* const* d_in, const int* in_sizes, int n_in,
                              void* d_out, int out_size) {
    const float* pred   = (const float*)d_in[0];
    const int*   target = (const int*)d_in[1];
    float* out = (float*)d_out;

    float* fA;  cudaGetSymbolAddress((void**)&fA, g_fA);
    float* fB;  cudaGetSymbolAddress((void**)&fB, g_fB);

    k_init<<<1, 1>>>();
    k_cpass<<<NHW / 256, 256>>>(target, fA);
    k_hpass<<<TOT / 256, 256>>>(fA, fB);
    k_wpass<<<TOT / 256, 256>>>(fB, fA);
    k_reduce<<<2048, 256>>>(pred, fA);
    k_final<<<1, 1>>>(out);
}

// round 5
// speedup vs baseline: 1.0624x; 1.0624x over previous
#include <cuda_runtime.h>
#include <cuda_bf16.h>
#include <math.h>

#define NB   16
#define CC   4
#define HH   256
#define WW   256
#define HW   (HH*WW)          // 65536
#define CHW  (CC*HW)          // 262144
#define TOT  (NB*CHW)         // 4194304

#define FINF 1e10f
#define WT   8                // w-tile width for the H-pass kernel

// Scratch (static device arrays — no allocation)
__device__ float g_dist[TOT];        // after C+H passes (squared dists)
__device__ float g_pnum[NB*HH];      // per-block partials from k2 (4096 blocks)
__device__ float g_pden[NB*HH];

// ---------------------------------------------------------------------------
// k1: fused C-pass + H-pass.
// Block = (n, w-tile of 8 columns), all 4 classes, all 256 h.
// smem tile sf[c][h][w] : 4*256*8 floats = 32 KB.
//  1. load target -> f0 (0 / INF) into smem
//  2. exact C-axis min-plus (length 4) in smem
//  3. exact H-axis expanding-window min-plus reading smem, write to global
// ---------------------------------------------------------------------------
__global__ void k1_ch(const int* __restrict__ target, float* __restrict__ dist) {
    __shared__ float sf[4 * 256 * WT];   // idx = c*2048 + h*8 + w

    const int n  = blockIdx.x >> 5;          // / (WW/WT=32)
    const int w0 = (blockIdx.x & 31) * WT;
    const int t  = threadIdx.x;
    const int nbase = n << 18;               // n*CHW

    // ---- load target as f0 ----
#pragma unroll
    for (int k = 0; k < 32; ++k) {
        int e = t + (k << 8);                // 0..8191
        int c = e >> 11;
        int hw = e & 2047;
        int h = hw >> 3;
        int w = hw & 7;
        int g = nbase + (c << 16) + (h << 8) + w0 + w;
        sf[e] = (target[g] == 0) ? FINF : 0.0f;
    }
    __syncthreads();

    // ---- C-axis min-plus (exact, length 4, values in {0, INF}) ----
#pragma unroll
    for (int k = 0; k < 8; ++k) {
        int p = t + (k << 8);                // 0..2047  (h*8+w)
        float a0 = sf[p];
        float a1 = sf[2048 + p];
        float a2 = sf[4096 + p];
        float a3 = sf[6144 + p];
        float o0 = fminf(fminf(a0, a1 + 1.0f), fminf(a2 + 4.0f, a3 + 9.0f));
        float o1 = fminf(fminf(a1, fminf(a0, a2) + 1.0f), a3 + 4.0f);
        float o2 = fminf(fminf(a2, fminf(a1, a3) + 1.0f), a0 + 4.0f);
        float o3 = fminf(fminf(a3, a2 + 1.0f), fminf(a1 + 4.0f, a0 + 9.0f));
        sf[p]        = o0;
        sf[2048 + p] = o1;
        sf[4096 + p] = o2;
        sf[6144 + p] = o3;
    }
    __syncthreads();

    // ---- H-axis exact expanding-window search in smem ----
#pragma unroll 4
    for (int k = 0; k < 32; ++k) {
        int e = t + (k << 8);
        int c = e >> 11;
        int hw = e & 2047;
        int h = hw >> 3;
        int w = hw & 7;
        float m = sf[e];
        if (m > 1.0f) {                      // m<=1 can't improve (r^2>=1)
            int rlo = h;
            int rhi = 255 - h;
            int rmax = rlo > rhi ? rlo : rhi;
            for (int r = 1; r <= rmax; ++r) {
                float r2 = (float)(r * r);
                if (r2 >= m) break;
                if (r <= rlo) m = fminf(m, sf[e - (r << 3)] + r2);
                if (r <= rhi) m = fminf(m, sf[e + (r << 3)] + r2);
            }
        }
        dist[nbase + (c << 16) + (h << 8) + w0 + w] = m;
    }
}

// ---------------------------------------------------------------------------
// k2: fused W-pass + softmax + partial reduction.
// Block = (n, h); 256 threads, thread = w. All 4 classes in smem.
// ---------------------------------------------------------------------------
__global__ void k2_wred(const float* __restrict__ dist,
                        const float* __restrict__ pred) {
    __shared__ float sd[4 * 256];
    __shared__ float snum[256];
    __shared__ float sden[256];

    const int n = blockIdx.x >> 8;
    const int h = blockIdx.x & 255;
    const int w = threadIdx.x;
    const int base = (n << 18) + (h << 8);   // n*CHW + h*W

    // load the 4 class lines (coalesced)
#pragma unroll
    for (int c = 0; c < CC; ++c)
        sd[(c << 8) + w] = dist[base + (c << 16) + w];
    __syncthreads();

    // W-axis exact expanding-window search per class
    float d[CC];
#pragma unroll
    for (int c = 0; c < CC; ++c) {
        const float* line = &sd[c << 8];
        float m = line[w];
        if (m > 1.0f) {
            int rlo = w;
            int rhi = 255 - w;
            int rmax = rlo > rhi ? rlo : rhi;
            for (int r = 1; r <= rmax; ++r) {
                float r2 = (float)(r * r);
                if (r2 >= m) break;
                if (r <= rlo) m = fminf(m, line[w - r] + r2);
                if (r <= rhi) m = fminf(m, line[w + r] + r2);
            }
        }
        d[c] = sqrtf(m);
    }

    // softmax over classes * dist
    float pr[CC];
#pragma unroll
    for (int c = 0; c < CC; ++c)
        pr[c] = pred[base + (c << 16) + w];
    float mx = fmaxf(fmaxf(pr[0], pr[1]), fmaxf(pr[2], pr[3]));
    float e0 = expf(pr[0] - mx);
    float e1 = expf(pr[1] - mx);
    float e2 = expf(pr[2] - mx);
    float e3 = expf(pr[3] - mx);
    float s  = e0 + e1 + e2 + e3;
    float num = (e0 * d[0] + e1 * d[1] + e2 * d[2] + e3 * d[3]) / s;
    float den = d[0] + d[1] + d[2] + d[3];

    // block reduction
    snum[w] = num;
    sden[w] = den;
    __syncthreads();
#pragma unroll
    for (int off = 128; off > 0; off >>= 1) {
        if (w < off) {
            snum[w] += snum[w + off];
            sden[w] += sden[w + off];
        }
        __syncthreads();
    }
    if (w == 0) {
        g_pnum[blockIdx.x] = snum[0];
        g_pden[blockIdx.x] = sden[0];
    }
}

// ---------------------------------------------------------------------------
// k3: final reduction over 4096 block partials
// ---------------------------------------------------------------------------
__global__ void k3_final(float* __restrict__ out) {
    __shared__ double dnum[256];
    __shared__ double dden[256];
    int t = threadIdx.x;
    double num = 0.0, den = 0.0;
#pragma unroll
    for (int k = 0; k < 16; ++k) {
        int i = t + (k << 8);
        num += (double)g_pnum[i];
        den += (double)g_pden[i];
    }
    dnum[t] = num;
    dden[t] = den;
    __syncthreads();
#pragma unroll
    for (int off = 128; off > 0; off >>= 1) {
        if (t < off) {
            dnum[t] += dnum[t + off];
            dden[t] += dden[t + off];
        }
        __syncthreads();
    }
    if (t == 0)
        out[0] = (float)(dnum[0] / (dden[0] + 1e-10));
}

// ---------------------------------------------------------------------------
extern "C" void kernel_launch(void* const* d_in, const int* in_sizes, int n_in,
                              void* d_out, int out_size) {
    const float* pred   = (const float*)d_in[0];
    const int*   target = (const int*)d_in[1];
    float* out = (float*)d_out;

    float* dist;
    cudaGetSymbolAddress((void**)&dist, g_dist);

    k1_ch  <<<NB * (WW / WT), 256>>>(target, dist);
    k2_wred<<<NB * HH,        256>>>(dist, pred);
    k3_final<<<1,             256>>>(out);
}

// round 6
// speedup vs baseline: 1.1615x; 1.0933x over previous
#include <cuda_runtime.h>
#include <cuda_bf16.h>
#include <math.h>

#define NB   16
#define CC   4
#define HH   256
#define WW   256
#define HW   (HH*WW)          // 65536
#define CHW  (CC*HW)          // 262144
#define TOT  (NB*CHW)         // 4194304

#define FINF 1e10f
#define WT   32               // w-tile width for the H-pass kernel

// Scratch (static device arrays — no allocation)
__device__ unsigned short g_rh[TOT];   // nearest-seed radius along H (0xFFFF = none)
__device__ float g_pnum[NB*HH];        // per-block partials from kB (4096 blocks)
__device__ float g_pden[NB*HH];

// ---------------------------------------------------------------------------
// kA: H-axis nearest-seed search on the BINARY mask (seed = target!=0).
// Block = (n, c, w-tile of 32). smem = 256h x 32w bytes (8KB).
// Search expands outward from each voxel; first seed found at radius r is the
// exact minimum (input is binary). Output uint16 radius, 0xFFFF if no seed.
// ---------------------------------------------------------------------------
__global__ void kA_h(const int* __restrict__ target,
                     unsigned short* __restrict__ rh) {
    __shared__ unsigned char sb[256 * WT];    // idx = h*32 + w'

    const int b  = blockIdx.x;
    const int n  = b >> 5;                    // / (CC * WW/WT) = /32
    const int c  = (b >> 3) & 3;
    const int w0 = (b & 7) * WT;
    const int t  = threadIdx.x;
    const int gbase = (n << 18) + (c << 16) + w0;

    // load binary seeds (coalesced, 128B/warp)
#pragma unroll
    for (int k = 0; k < 32; ++k) {
        int e  = t + (k << 8);                // 0..8191 ; h = e>>5, w' = e&31
        int h  = e >> 5;
        int wp = e & 31;
        sb[e] = (target[gbase + (h << 8) + wp] != 0) ? 1 : 0;
    }
    __syncthreads();

    // expanding first-seed search per voxel
#pragma unroll 4
    for (int k = 0; k < 32; ++k) {
        int e  = t + (k << 8);
        int h  = e >> 5;
        int wp = e & 31;
        unsigned short r = 0xFFFF;
        if (sb[e]) {
            r = 0;
        } else {
            int rlo = h;
            int rhi = 255 - h;
            int rmax = rlo > rhi ? rlo : rhi;
            for (int rr = 1; rr <= rmax; ++rr) {
                int hit = 0;
                if (rr <= rlo) hit |= sb[e - (rr << 5)];
                if (rr <= rhi) hit |= sb[e + (rr << 5)];
                if (hit) { r = (unsigned short)rr; break; }
            }
        }
        rh[gbase + (h << 8) + wp] = r;
    }
}

// ---------------------------------------------------------------------------
// kB: fused W-pass + C-pass + softmax + partial reduction.
// Block = (n, h); 256 threads, thread = w. All 4 classes in smem.
// W-search on g = rh^2 (exact ints), then length-4 C min-plus in registers,
// then sqrt/softmax/reduce.
// ---------------------------------------------------------------------------
__global__ void kB_wcred(const unsigned short* __restrict__ rh,
                         const float* __restrict__ pred) {
    __shared__ float sd[4 * 256];
    __shared__ float snum[256];
    __shared__ float sden[256];

    const int n = blockIdx.x >> 8;
    const int h = blockIdx.x & 255;
    const int w = threadIdx.x;
    const int base = (n << 18) + (h << 8);   // n*CHW + h*W

    // load + decode the 4 class lines (coalesced)
#pragma unroll
    for (int c = 0; c < CC; ++c) {
        int r = rh[base + (c << 16) + w];
        sd[(c << 8) + w] = (r == 0xFFFF) ? FINF : (float)(r * r);
    }
    __syncthreads();

    // W-axis exact expanding-window min-plus per class
    float e[CC];
#pragma unroll
    for (int c = 0; c < CC; ++c) {
        const float* line = &sd[c << 8];
        float m = line[w];
        if (m > 1.0f) {
            int rlo = w;
            int rhi = 255 - w;
            int rmax = rlo > rhi ? rlo : rhi;
            for (int r = 1; r <= rmax; ++r) {
                float r2 = (float)(r * r);
                if (r2 >= m) break;
                if (r <= rlo) m = fminf(m, line[w - r] + r2);
                if (r <= rhi) m = fminf(m, line[w + r] + r2);
            }
        }
        e[c] = m;
    }

    // C-axis min-plus (exact, length 4)
    float m0 = fminf(fminf(e[0], e[1] + 1.0f), fminf(e[2] + 4.0f, e[3] + 9.0f));
    float m1 = fminf(fminf(e[1], fminf(e[0], e[2]) + 1.0f), e[3] + 4.0f);
    float m2 = fminf(fminf(e[2], fminf(e[1], e[3]) + 1.0f), e[0] + 4.0f);
    float m3 = fminf(fminf(e[3], e[2] + 1.0f), fminf(e[1] + 4.0f, e[0] + 9.0f));

    float d0 = sqrtf(m0);
    float d1 = sqrtf(m1);
    float d2 = sqrtf(m2);
    float d3 = sqrtf(m3);

    // softmax over classes * dist
    float p0 = pred[base + w];
    float p1 = pred[base + (1 << 16) + w];
    float p2 = pred[base + (2 << 16) + w];
    float p3 = pred[base + (3 << 16) + w];
    float mx = fmaxf(fmaxf(p0, p1), fmaxf(p2, p3));
    float e0 = __expf(p0 - mx);
    float e1 = __expf(p1 - mx);
    float e2 = __expf(p2 - mx);
    float e3 = __expf(p3 - mx);
    float s  = e0 + e1 + e2 + e3;
    float num = __fdividef(e0 * d0 + e1 * d1 + e2 * d2 + e3 * d3, s);
    float den = d0 + d1 + d2 + d3;

    // block reduction
    snum[w] = num;
    sden[w] = den;
    __syncthreads();
#pragma unroll
    for (int off = 128; off > 0; off >>= 1) {
        if (w < off) {
            snum[w] += snum[w + off];
            sden[w] += sden[w + off];
        }
        __syncthreads();
    }
    if (w == 0) {
        g_pnum[blockIdx.x] = snum[0];
        g_pden[blockIdx.x] = sden[0];
    }
}

// ---------------------------------------------------------------------------
// k3: final reduction over 4096 block partials
// ---------------------------------------------------------------------------
__global__ void k3_final(float* __restrict__ out) {
    __shared__ double dnum[256];
    __shared__ double dden[256];
    int t = threadIdx.x;
    double num = 0.0, den = 0.0;
#pragma unroll
    for (int k = 0; k < 16; ++k) {
        int i = t + (k << 8);
        num += (double)g_pnum[i];
        den += (double)g_pden[i];
    }
    dnum[t] = num;
    dden[t] = den;
    __syncthreads();
#pragma unroll
    for (int off = 128; off > 0; off >>= 1) {
        if (t < off) {
            dnum[t] += dnum[t + off];
            dden[t] += dden[t + off];
        }
        __syncthreads();
    }
    if (t == 0)
        out[0] = (float)(dnum[0] / (dden[0] + 1e-10));
}

// ---------------------------------------------------------------------------
extern "C" void kernel_launch(void* const* d_in, const int* in_sizes, int n_in,
                              void* d_out, int out_size) {
    const float* pred   = (const float*)d_in[0];
    const int*   target = (const int*)d_in[1];
    float* out = (float*)d_out;

    unsigned short* rh;
    cudaGetSymbolAddress((void**)&rh, g_rh);

    kA_h    <<<NB * CC * (WW / WT), 256>>>(target, rh);
    kB_wcred<<<NB * HH,             256>>>(rh, pred);
    k3_final<<<1,                   256>>>(out);
}

// round 8
// speedup vs baseline: 1.2962x; 1.1159x over previous
#include <cuda_runtime.h>
#include <cuda_bf16.h>
#include <math.h>

#define NB   16
#define CC   4
#define HH   256
#define WW   256
#define HW   (HH*WW)          // 65536
#define CHW  (CC*HW)          // 262144
#define TOT  (NB*CHW)         // 4194304

#define FINF 1e10f
#define WT   8                // w-tile width for kB

// Scratch (static device arrays — no allocation)
__device__ unsigned short g_rw[TOT];   // nearest-seed radius along W (0xFFFF = none)
__device__ float g_pnum[512];          // per-block partials from kB
__device__ float g_pden[512];

// ---------------------------------------------------------------------------
// kA: W-axis nearest-seed search on the BINARY mask (seed = target!=0).
// Block = (n, c, h-tile of 32 rows). Row bitmasks built via ballot on
// coalesced loads; nearest set bit via clz/ffs word scan (exact).
// ---------------------------------------------------------------------------
__global__ void kA_w(const int* __restrict__ target,
                     unsigned short* __restrict__ rw) {
    __shared__ unsigned int srow[32][8];      // [local row][word]

    const int b    = blockIdx.x;
    const int n    = b >> 5;                  // /(CC*8)
    const int c    = (b >> 3) & 3;
    const int h0   = (b & 7) << 5;            // *32
    const int t    = threadIdx.x;
    const int warp = t >> 5;
    const int lane = t & 31;
    const int gbase = (n << 18) + (c << 16);

    // ---- build row bitmasks (8 warps x 4 rows) ----
#pragma unroll
    for (int rr = 0; rr < 4; ++rr) {
        const int hr = (warp << 2) + rr;      // local row 0..31
        const int h  = h0 + hr;
        unsigned int word = 0;
#pragma unroll
        for (int q = 0; q < 8; ++q) {
            int v = target[gbase + (h << 8) + (q << 5) + lane];
            unsigned int bal = __ballot_sync(0xFFFFFFFFu, v != 0);
            if (lane == q) word = bal;
        }
        if (lane < 8) srow[hr][lane] = word;
    }
    __syncthreads();

    // ---- nearest-set-bit distance per voxel; thread t owns column w=t ----
    const int w    = t;
    const int wi   = w >> 5;
    const int bpos = w & 31;
    const unsigned int maskLo = 0xFFFFFFFFu >> (31 - bpos);  // bits <= bpos
    const unsigned int maskHi = 0xFFFFFFFFu << bpos;         // bits >= bpos

#pragma unroll 4
    for (int hr = 0; hr < 32; ++hr) {
        const unsigned int own = srow[hr][wi];
        int dd = 1 << 20, du = 1 << 20;

        unsigned int m = own & maskLo;
        if (m) {
            dd = bpos - (31 - __clz(m));
        } else {
            for (int j = wi - 1; j >= 0; --j) {
                unsigned int wj = srow[hr][j];
                if (wj) { dd = bpos + ((wi - j) << 5) - (31 - __clz(wj)); break; }
            }
        }
        m = own & maskHi;
        if (m) {
            du = (__ffs(m) - 1) - bpos;
        } else {
            for (int j = wi + 1; j < 8; ++j) {
                unsigned int wj = srow[hr][j];
                if (wj) { du = ((j << 5) + (__ffs(wj) - 1)) - w; break; }
            }
        }
        int r = dd < du ? dd : du;
        if (r > 0xFFFF) r = 0xFFFF;
        rw[gbase + ((h0 + hr) << 8) + w] = (unsigned short)r;
    }
}

// ---------------------------------------------------------------------------
// kB: fused H-pass (min-plus, exact expanding window with early stop) +
// C-pass + softmax + partial reduction.
// Block = (n, w-tile of 8). smem sf[c][h][w'] = 4*256*8 floats (32 KB).
// ---------------------------------------------------------------------------
__global__ void kB_hcred(const unsigned short* __restrict__ rw,
                         const float* __restrict__ pred) {
    __shared__ float sf[4 * 256 * WT];   // c*2048 + h*8 + w'
    __shared__ float snum[256];
    __shared__ float sden[256];

    const int n  = blockIdx.x >> 5;
    const int w0 = (blockIdx.x & 31) * WT;
    const int t  = threadIdx.x;
    const int nbase = n << 18;

    // ---- load rw tile (uint4 = 8 u16 per (c,h) row segment), square it ----
#pragma unroll
    for (int k = 0; k < 4; ++k) {
        int e = t + (k << 8);            // 0..1023: c = e>>8, h = e&255
        int c = e >> 8;
        int h = e & 255;
        uint4 v = *(const uint4*)(rw + nbase + (c << 16) + (h << 8) + w0);
        float* dst = &sf[(c << 11) + (h << 3)];
        unsigned r0 = v.x & 0xFFFFu, r1 = v.x >> 16;
        unsigned r2 = v.y & 0xFFFFu, r3 = v.y >> 16;
        unsigned r4 = v.z & 0xFFFFu, r5 = v.z >> 16;
        unsigned r6 = v.w & 0xFFFFu, r7 = v.w >> 16;
        float4 a, bq;
        a.x  = (r0 == 0xFFFFu) ? FINF : (float)(r0 * r0);
        a.y  = (r1 == 0xFFFFu) ? FINF : (float)(r1 * r1);
        a.z  = (r2 == 0xFFFFu) ? FINF : (float)(r2 * r2);
        a.w  = (r3 == 0xFFFFu) ? FINF : (float)(r3 * r3);
        bq.x = (r4 == 0xFFFFu) ? FINF : (float)(r4 * r4);
        bq.y = (r5 == 0xFFFFu) ? FINF : (float)(r5 * r5);
        bq.z = (r6 == 0xFFFFu) ? FINF : (float)(r6 * r6);
        bq.w = (r7 == 0xFFFFu) ? FINF : (float)(r7 * r7);
        *(float4*)(dst)     = a;
        *(float4*)(dst + 4) = bq;
    }
    __syncthreads();

    // ---- per voxel: H-search (exact), C min-plus, softmax, accumulate ----
    // voxel space: 256 h x 8 w' = 2048 -> 8 iterations of 256 threads
    float num = 0.0f, den = 0.0f;
#pragma unroll
    for (int k = 0; k < 8; ++k) {
        int e  = t + (k << 8);           // 0..2047: w' = e&7, h = e>>3 (0..255)
        int wp = e & 7;
        int h  = e >> 3;

        float d[CC];
#pragma unroll
        for (int c = 0; c < CC; ++c) {
            const float* col = &sf[(c << 11) + wp];
            float m = col[h << 3];
            if (m > 1.0f) {
                int rlo = h;
                int rhi = 255 - h;
                int rmax = rlo > rhi ? rlo : rhi;
                for (int r = 1; r <= rmax; ++r) {
                    float r2 = (float)(r * r);
                    if (r2 >= m) break;
                    if (r <= rlo) m = fminf(m, col[(h - r) << 3] + r2);
                    if (r <= rhi) m = fminf(m, col[(h + r) << 3] + r2);
                }
            }
            d[c] = m;
        }

        // C-axis min-plus (exact, length 4)
        float m0 = fminf(fminf(d[0], d[1] + 1.0f), fminf(d[2] + 4.0f, d[3] + 9.0f));
        float m1 = fminf(fminf(d[1], fminf(d[0], d[2]) + 1.0f), d[3] + 4.0f);
        float m2 = fminf(fminf(d[2], fminf(d[1], d[3]) + 1.0f), d[0] + 4.0f);
        float m3 = fminf(fminf(d[3], d[2] + 1.0f), fminf(d[1] + 4.0f, d[0] + 9.0f));

        float d0 = sqrtf(m0);
        float d1 = sqrtf(m1);
        float d2 = sqrtf(m2);
        float d3 = sqrtf(m3);

        int pbase = nbase + (h << 8) + w0 + wp;
        float p0 = pred[pbase];
        float p1 = pred[pbase + (1 << 16)];
        float p2 = pred[pbase + (2 << 16)];
        float p3 = pred[pbase + (3 << 16)];
        float mx = fmaxf(fmaxf(p0, p1), fmaxf(p2, p3));
        float e0 = __expf(p0 - mx);
        float e1 = __expf(p1 - mx);
        float e2 = __expf(p2 - mx);
        float e3 = __expf(p3 - mx);
        float s  = e0 + e1 + e2 + e3;
        num += __fdividef(e0 * d0 + e1 * d1 + e2 * d2 + e3 * d3, s);
        den += d0 + d1 + d2 + d3;
    }

    // ---- block reduction ----
    snum[t] = num;
    sden[t] = den;
    __syncthreads();
#pragma unroll
    for (int off = 128; off > 0; off >>= 1) {
        if (t < off) {
            snum[t] += snum[t + off];
            sden[t] += sden[t + off];
        }
        __syncthreads();
    }
    if (t == 0) {
        g_pnum[blockIdx.x] = snum[0];
        g_pden[blockIdx.x] = sden[0];
    }
}

// ---------------------------------------------------------------------------
// k3: final reduction over 512 block partials
// ---------------------------------------------------------------------------
__global__ void k3_final(float* __restrict__ out) {
    __shared__ double dnum[256];
    __shared__ double dden[256];
    int t = threadIdx.x;
    double num = (double)g_pnum[t] + (double)g_pnum[t + 256];
    double den = (double)g_pden[t] + (double)g_pden[t + 256];
    dnum[t] = num;
    dden[t] = den;
    __syncthreads();
#pragma unroll
    for (int off = 128; off > 0; off >>= 1) {
        if (t < off) {
            dnum[t] += dnum[t + off];
            dden[t] += dden[t + off];
        }
        __syncthreads();
    }
    if (t == 0)
        out[0] = (float)(dnum[0] / (dden[0] + 1e-10));
}

// ---------------------------------------------------------------------------
extern "C" void kernel_launch(void* const* d_in, const int* in_sizes, int n_in,
                              void* d_out, int out_size) {
    const float* pred   = (const float*)d_in[0];
    const int*   target = (const int*)d_in[1];
    float* out = (float*)d_out;

    unsigned short* rw;
    cudaGetSymbolAddress((void**)&rw, g_rw);

    kA_w    <<<NB * CC * (HH / 32), 256>>>(target, rw);
    kB_hcred<<<NB * (WW / WT),      256>>>(rw, pred);
    k3_final<<<1,                   256>>>(out);
}